// round 4
// baseline (speedup 1.0000x reference)
#include <cuda_runtime.h>
#include <cuda_bf16.h>
#include <cstdint>
#include <cstddef>

// ---------------------------------------------------------------------------
// MultiCELoss: KL(softmax(scores) || softmax(cos(anchor, tgt))) / (R-1) mean
//            + ALPHA * mean_b( logsumexp_j(scale * a_b . t_j) - scale * a_b . t_b )
// Shapes: B=4096, R=18, D=256.  Heavy part: 4096 x 69632 x 256 GEMM fused with
// per-row online logsumexp (flash-style), bf16 mma.sync, fp32 accumulate.
// Fully deterministic (no float atomics; fixed reduction trees).
// ---------------------------------------------------------------------------

#define C_ALPHA 0.2f
#define C_BETA  1.0f
#define C_EPS   1e-8f

// Problem-size scratch (device globals; allocation-free per harness rules)
#define MAXB 4096
#define MAXR 18
#define DD   256
#define NSPLIT 32

__device__ __align__(16) __nv_bfloat16 g_anchor[(size_t)MAXB * DD];
__device__ __align__(16) __nv_bfloat16 g_targets[(size_t)MAXB * (MAXR - 1) * DD];
__device__ float g_diag[MAXB];
__device__ float g_kl[MAXB];
__device__ float g_part_m[(size_t)NSPLIT * MAXB];
__device__ float g_part_l[(size_t)NSPLIT * MAXB];
__device__ float g_bsum[64];

// ---------------------------------------------------------------------------
// PTX helpers
// ---------------------------------------------------------------------------
__device__ __forceinline__ void cp_async16(uint32_t saddr, const void* gaddr) {
    asm volatile("cp.async.cg.shared.global [%0], [%1], 16;\n"
                 :: "r"(saddr), "l"(gaddr) : "memory");
}
__device__ __forceinline__ void cp_commit() {
    asm volatile("cp.async.commit_group;\n" ::: "memory");
}
template <int N>
__device__ __forceinline__ void cp_wait() {
    asm volatile("cp.async.wait_group %0;\n" :: "n"(N) : "memory");
}
__device__ __forceinline__ void ldsm4(uint32_t* r, uint32_t addr) {
    asm volatile("ldmatrix.sync.aligned.m8n8.x4.shared.b16 {%0,%1,%2,%3}, [%4];\n"
                 : "=r"(r[0]), "=r"(r[1]), "=r"(r[2]), "=r"(r[3]) : "r"(addr));
}
__device__ __forceinline__ void mma16816(float* c, const uint32_t* a, uint32_t b0, uint32_t b1) {
    asm volatile("mma.sync.aligned.m16n8k16.row.col.f32.bf16.bf16.f32 "
                 "{%0,%1,%2,%3}, {%4,%5,%6,%7}, {%8,%9}, {%0,%1,%2,%3};\n"
                 : "+f"(c[0]), "+f"(c[1]), "+f"(c[2]), "+f"(c[3])
                 : "r"(a[0]), "r"(a[1]), "r"(a[2]), "r"(a[3]), "r"(b0), "r"(b1));
}

// ---------------------------------------------------------------------------
// Kernel 1: convert features (fp32) -> bf16 anchors + reordered bf16 targets
// targets[j]: j <  B : f3[j, 1]           (pos)
//             j >= B : f3[(j-B)/(R-2), 2 + (j-B)%(R-2)]  (negs)
// ---------------------------------------------------------------------------
__global__ void convert_kernel(const float* __restrict__ f, int B, int R, int D) {
    int rr = blockIdx.x;
    int t  = threadIdx.x;   // 64 threads, each handles float4 chunks
    size_t src_row;
    __nv_bfloat16* dst;
    if (rr < B) {
        src_row = (size_t)rr * R;
        dst = g_anchor + (size_t)rr * D;
    } else {
        int j = rr - B;
        int src_b, src_k;
        if (j < B) { src_b = j; src_k = 1; }
        else { int idx = j - B; src_b = idx / (R - 2); src_k = 2 + idx % (R - 2); }
        src_row = (size_t)src_b * R + src_k;
        dst = g_targets + (size_t)j * D;
    }
    const float4* src = (const float4*)(f + src_row * D);
    int n4 = D >> 2;
    for (int d4 = t; d4 < n4; d4 += 64) {
        float4 v = src[d4];
        __nv_bfloat162 lo = __floats2bfloat162_rn(v.x, v.y);
        __nv_bfloat162 hi = __floats2bfloat162_rn(v.z, v.w);
        ((__nv_bfloat162*)dst)[d4 * 2 + 0] = lo;
        ((__nv_bfloat162*)dst)[d4 * 2 + 1] = hi;
    }
}

// ---------------------------------------------------------------------------
// Kernel 2: per-anchor stats — norms, 17 cosines, KL vs softmax(scores),
// diagonal dot (anchor . pos).  All fp32 (cheap, reads features once).
// ---------------------------------------------------------------------------
__global__ void stats_kernel(const float* __restrict__ f,
                             const float* __restrict__ scores,
                             int B, int R, int D) {
    int b = blockIdx.x, t = threadIdx.x;  // 128 threads
    const float2* base2 = (const float2*)(f + (size_t)b * R * D);
    int D2 = D >> 1;
    __shared__ float s_dot[32], s_nrm[32], s_red[8];

    for (int k = 0; k < R; k++) {
        float dp = 0.f, sq = 0.f;
        for (int d = t; d < D2; d += 128) {
            float2 xa = base2[d];
            float2 x  = base2[(size_t)k * D2 + d];
            dp += xa.x * x.x + xa.y * x.y;
            sq += x.x * x.x + x.y * x.y;
        }
        #pragma unroll
        for (int o = 16; o > 0; o >>= 1) {
            dp += __shfl_down_sync(0xffffffffu, dp, o);
            sq += __shfl_down_sync(0xffffffffu, sq, o);
        }
        if ((t & 31) == 0) { s_red[t >> 5] = dp; s_red[4 + (t >> 5)] = sq; }
        __syncthreads();
        if (t == 0) {
            s_dot[k] = s_red[0] + s_red[1] + s_red[2] + s_red[3];
            s_nrm[k] = s_red[4] + s_red[5] + s_red[6] + s_red[7];
        }
        __syncthreads();
    }

    if (t < 32) {
        int k = t;
        bool valid = (k >= 1 && k < R);
        float an = fmaxf(sqrtf(s_nrm[0]), C_EPS);
        float cosv = valid ? s_dot[k] / (an * fmaxf(sqrtf(s_nrm[k]), C_EPS)) : -1e30f;
        float sc   = valid ? scores[(size_t)b * (R - 1) + (k - 1)] : -1e30f;

        float cmax = cosv, smax = sc;
        #pragma unroll
        for (int o = 16; o > 0; o >>= 1) {
            cmax = fmaxf(cmax, __shfl_xor_sync(0xffffffffu, cmax, o));
            smax = fmaxf(smax, __shfl_xor_sync(0xffffffffu, smax, o));
        }
        float c_e  = valid ? __expf(cosv - cmax) : 0.f;
        float ce_e = valid ? __expf(sc - smax)   : 0.f;
        float csum = c_e, ssum = ce_e;
        #pragma unroll
        for (int o = 16; o > 0; o >>= 1) {
            csum += __shfl_xor_sync(0xffffffffu, csum, o);
            ssum += __shfl_xor_sync(0xffffffffu, ssum, o);
        }
        float emb_log = cosv - cmax - logf(csum);   // log_softmax(cos)
        float lce     = sc - smax - logf(ssum);     // log(softmax(scores))
        float ce      = ce_e / ssum;
        float term    = valid ? ce * (lce - emb_log) : 0.f;
        #pragma unroll
        for (int o = 16; o > 0; o >>= 1)
            term += __shfl_xor_sync(0xffffffffu, term, o);
        if (t == 0) {
            g_kl[b]   = term / (float)(R - 1);
            g_diag[b] = s_dot[1];   // raw anchor.pos dot (scale applied later)
        }
    }
}

// ---------------------------------------------------------------------------
// Kernel 3: fused GEMM + online logsumexp.
// BM=BN=128, K=256.  8 warps, each owns 16 anchor rows (full rows -> no
// cross-warp softmax comms).  A-tile resident; B-tile double-buffered cp.async.
// Padded smem row stride 528B (conflict-free LDSM).
// ---------------------------------------------------------------------------
#define BM 128
#define BN 128
#define SSTRIDE 528                  // bytes per smem row (512 data + 16 pad)
#define TILE_SMEM (128 * SSTRIDE)    // 67584 B
#define GEMM_SMEM (3 * TILE_SMEM)    // A + 2x B = 202752 B

__device__ __forceinline__ void load_tile_async(uint32_t sbase,
                                                const __nv_bfloat16* gsrc,
                                                int tid) {
    const char* src = (const char*)gsrc;
    #pragma unroll
    for (int i = 0; i < 16; i++) {
        int c   = i * 256 + tid;       // 4096 x 16B chunks
        int row = c >> 5, col = c & 31;
        cp_async16(sbase + row * SSTRIDE + col * 16, src + row * 512 + col * 16);
    }
    cp_commit();
}

__global__ __launch_bounds__(256, 1)
void gemm_lse_kernel(const float* __restrict__ logit_scale_ptr,
                     int B, int ntiles) {
    extern __shared__ char smem[];
    const int tid  = threadIdx.x;
    const int warp = tid >> 5, lane = tid & 31;
    const int split = blockIdx.x;      // 0..NSPLIT-1
    const int mtile = blockIdx.y;      // 0..B/128-1
    const float scale = __ldg(logit_scale_ptr);

    const uint32_t As_b  = (uint32_t)__cvta_generic_to_shared(smem);
    const uint32_t Bs_b0 = As_b + TILE_SMEM;
    const uint32_t Bs_b1 = As_b + 2 * TILE_SMEM;

    // work partition over N tiles
    int tps = ntiles / NSPLIT, rem = ntiles % NSPLIT;
    int my_nt = tps + (split < rem ? 1 : 0);
    int tbase = split * tps + (split < rem ? split : rem);

    // A tile (anchors) load — stays resident
    load_tile_async(As_b, g_anchor + (size_t)mtile * BM * DD, tid);
    // B tile 0
    if (my_nt > 0)
        load_tile_async(Bs_b0, g_targets + (size_t)(tbase)*BN * DD, tid);

    // ldmatrix in-tile offsets
    const int q = lane >> 3;
    const uint32_t a_off = (uint32_t)((warp * 16 + (lane & 7) + (q & 1) * 8) * SSTRIDE
                                      + (q >> 1) * 16);
    const uint32_t b_off = (uint32_t)(((lane & 7) + (q >> 1) * 8) * SSTRIDE
                                      + (q & 1) * 16);

    float m_lo = -1e30f, l_lo = 0.f, m_hi = -1e30f, l_hi = 0.f;

    for (int i = 0; i < my_nt; i++) {
        if (i + 1 < my_nt)
            load_tile_async((i & 1) ? Bs_b0 : Bs_b1,
                            g_targets + (size_t)(tbase + i + 1) * BN * DD, tid);
        if (i + 1 < my_nt) cp_wait<1>(); else cp_wait<0>();
        __syncthreads();

        const uint32_t Bb = (i & 1) ? Bs_b1 : Bs_b0;
        float c[16][4];
        #pragma unroll
        for (int f2 = 0; f2 < 16; f2++) { c[f2][0] = c[f2][1] = c[f2][2] = c[f2][3] = 0.f; }

        #pragma unroll
        for (int k = 0; k < 16; k++) {
            uint32_t a[4];
            ldsm4(a, As_b + a_off + k * 32);
            #pragma unroll
            for (int nf2 = 0; nf2 < 8; nf2++) {
                uint32_t bb[4];
                ldsm4(bb, Bb + b_off + nf2 * (16 * SSTRIDE) + k * 32);
                mma16816(c[2 * nf2],     a, bb[0], bb[1]);
                mma16816(c[2 * nf2 + 1], a, bb[2], bb[3]);
            }
        }

        // ---- online logsumexp update (rows lane/4 and lane/4+8 of this warp)
        float vlo = -1e30f, vhi = -1e30f;
        #pragma unroll
        for (int f2 = 0; f2 < 16; f2++) {
            c[f2][0] *= scale; c[f2][1] *= scale; c[f2][2] *= scale; c[f2][3] *= scale;
            vlo = fmaxf(vlo, fmaxf(c[f2][0], c[f2][1]));
            vhi = fmaxf(vhi, fmaxf(c[f2][2], c[f2][3]));
        }
        vlo = fmaxf(vlo, __shfl_xor_sync(0xffffffffu, vlo, 1));
        vlo = fmaxf(vlo, __shfl_xor_sync(0xffffffffu, vlo, 2));
        vhi = fmaxf(vhi, __shfl_xor_sync(0xffffffffu, vhi, 1));
        vhi = fmaxf(vhi, __shfl_xor_sync(0xffffffffu, vhi, 2));

        bool need = (vlo > m_lo - 25.f) || (vhi > m_hi - 25.f);
        if (__ballot_sync(0xffffffffu, need)) {
            float nm_lo = fmaxf(m_lo, vlo), nm_hi = fmaxf(m_hi, vhi);
            float s_lo = 0.f, s_hi = 0.f;
            #pragma unroll
            for (int f2 = 0; f2 < 16; f2++) {
                s_lo += __expf(c[f2][0] - nm_lo) + __expf(c[f2][1] - nm_lo);
                s_hi += __expf(c[f2][2] - nm_hi) + __expf(c[f2][3] - nm_hi);
            }
            s_lo += __shfl_xor_sync(0xffffffffu, s_lo, 1);
            s_lo += __shfl_xor_sync(0xffffffffu, s_lo, 2);
            s_hi += __shfl_xor_sync(0xffffffffu, s_hi, 1);
            s_hi += __shfl_xor_sync(0xffffffffu, s_hi, 2);
            l_lo = l_lo * __expf(m_lo - nm_lo) + s_lo; m_lo = nm_lo;
            l_hi = l_hi * __expf(m_hi - nm_hi) + s_hi; m_hi = nm_hi;
        }
        __syncthreads();
    }

    if ((lane & 3) == 0) {
        int r0 = mtile * BM + warp * 16 + (lane >> 2);
        size_t o = (size_t)split * B + r0;
        g_part_m[o]     = m_lo;  g_part_l[o]     = l_lo;
        g_part_m[o + 8] = m_hi;  g_part_l[o + 8] = l_hi;
    }
}

// ---------------------------------------------------------------------------
// Kernel 4: merge split partials -> lse, combine with KL + diag, block-reduce
// ---------------------------------------------------------------------------
__global__ void merge_kernel(const float* __restrict__ logit_scale_ptr, int B) {
    int b = blockIdx.x * 256 + threadIdx.x;
    float scale = __ldg(logit_scale_ptr);
    float M = -1e30f;
    #pragma unroll
    for (int i = 0; i < NSPLIT; i++) M = fmaxf(M, g_part_m[(size_t)i * B + b]);
    float L = 0.f;
    #pragma unroll
    for (int i = 0; i < NSPLIT; i++)
        L += g_part_l[(size_t)i * B + b] * __expf(g_part_m[(size_t)i * B + b] - M);
    float lse = M + logf(L);
    float val = C_BETA * g_kl[b] + C_ALPHA * (lse - scale * g_diag[b]);

    __shared__ float sm[256];
    sm[threadIdx.x] = val;
    __syncthreads();
    #pragma unroll
    for (int s = 128; s > 0; s >>= 1) {
        if (threadIdx.x < s) sm[threadIdx.x] += sm[threadIdx.x + s];
        __syncthreads();
    }
    if (threadIdx.x == 0) g_bsum[blockIdx.x] = sm[0];
}

__global__ void final_kernel(float* out, int B, int nb) {
    if (threadIdx.x == 0) {
        float s = 0.f;
        for (int i = 0; i < nb; i++) s += g_bsum[i];
        out[0] = s / (float)B;
    }
}

// ---------------------------------------------------------------------------
extern "C" void kernel_launch(void* const* d_in, const int* in_sizes, int n_in,
                              void* d_out, int out_size) {
    const float* features = (const float*)d_in[0];
    const float* scores   = (const float*)d_in[1];
    const float* lscale   = (const float*)d_in[3];
    float* out = (float*)d_out;

    int B   = in_sizes[2];
    int Rm1 = in_sizes[1] / B;
    int R   = Rm1 + 1;
    int D   = in_sizes[0] / (B * R);   // expected 256

    cudaFuncSetAttribute(gemm_lse_kernel,
                         cudaFuncAttributeMaxDynamicSharedMemorySize, GEMM_SMEM);

    // 1. bf16 conversion / target reorder
    convert_kernel<<<B * R, 64>>>(features, B, R, D);
    // 2. norms / cos / KL / diagonal (fp32)
    stats_kernel<<<B, 128>>>(features, scores, B, R, D);
    // 3. fused GEMM + online logsumexp
    int Ntot   = B * Rm1;          // 69632
    int ntiles = Ntot / BN;        // 544
    dim3 grid(NSPLIT, B / BM);     // (32, 32)
    gemm_lse_kernel<<<grid, 256, GEMM_SMEM>>>(lscale, B, ntiles);
    // 4. merge + reduce
    int nb = B / 256;              // 16
    merge_kernel<<<nb, 256>>>(lscale, B);
    final_kernel<<<1, 32>>>(out, B, nb);
}

// round 10
// speedup vs baseline: 1.0538x; 1.0538x over previous
#include <cuda_runtime.h>
#include <cuda_bf16.h>
#include <cstdint>
#include <cstddef>

// ---------------------------------------------------------------------------
// MultiCELoss: KL(softmax(scores) || softmax(cos(anchor, tgt))) / (R-1) mean
//            + ALPHA * mean_b( logsumexp_j(scale * a_b . t_j) - scale * a_b . t_b )
// B=4096, R=18, D=256.  Heavy part: 4096 x 69632 x 256 GEMM fused with
// per-row online logsumexp, bf16 mma.sync (HMMA), fp32 accumulate.
// NOTE: harness PTX target is compute_103 (no 'a') -> tcgen05/TMEM unavailable;
// mma.sync is the fastest available tensor path.  Deterministic (no float
// atomics; fixed reduction trees).
// ---------------------------------------------------------------------------

#define C_ALPHA 0.2f
#define C_BETA  1.0f
#define C_EPS   1e-8f

#define MAXB 4096
#define MAXR 18
#define DD   256
#define NSPLIT 32

__device__ __align__(16) __nv_bfloat16 g_anchor[(size_t)MAXB * DD];
__device__ __align__(16) __nv_bfloat16 g_targets[(size_t)MAXB * (MAXR - 1) * DD];
__device__ float g_diag[MAXB];
__device__ float g_kl[MAXB];
__device__ float g_part_m[(size_t)NSPLIT * MAXB];
__device__ float g_part_l[(size_t)NSPLIT * MAXB];
__device__ float g_bsum[64];

// ---------------------------------------------------------------------------
// PTX helpers
// ---------------------------------------------------------------------------
__device__ __forceinline__ void cp_async16(uint32_t saddr, const void* gaddr) {
    asm volatile("cp.async.cg.shared.global [%0], [%1], 16;\n"
                 :: "r"(saddr), "l"(gaddr) : "memory");
}
__device__ __forceinline__ void cp_commit() {
    asm volatile("cp.async.commit_group;\n" ::: "memory");
}
template <int N>
__device__ __forceinline__ void cp_wait() {
    asm volatile("cp.async.wait_group %0;\n" :: "n"(N) : "memory");
}
__device__ __forceinline__ void ldsm4(uint32_t* r, uint32_t addr) {
    asm volatile("ldmatrix.sync.aligned.m8n8.x4.shared.b16 {%0,%1,%2,%3}, [%4];\n"
                 : "=r"(r[0]), "=r"(r[1]), "=r"(r[2]), "=r"(r[3]) : "r"(addr));
}
__device__ __forceinline__ void mma16816(float* c, const uint32_t* a, uint32_t b0, uint32_t b1) {
    asm volatile("mma.sync.aligned.m16n8k16.row.col.f32.bf16.bf16.f32 "
                 "{%0,%1,%2,%3}, {%4,%5,%6,%7}, {%8,%9}, {%0,%1,%2,%3};\n"
                 : "+f"(c[0]), "+f"(c[1]), "+f"(c[2]), "+f"(c[3])
                 : "r"(a[0]), "r"(a[1]), "r"(a[2]), "r"(a[3]), "r"(b0), "r"(b1));
}

// ---------------------------------------------------------------------------
// Kernel 1: convert features (fp32) -> bf16 anchors + reordered bf16 targets
// ---------------------------------------------------------------------------
__global__ void convert_kernel(const float* __restrict__ f, int B, int R, int D) {
    int rr = blockIdx.x;
    int t  = threadIdx.x;   // 64 threads
    size_t src_row;
    __nv_bfloat16* dst;
    if (rr < B) {
        src_row = (size_t)rr * R;
        dst = g_anchor + (size_t)rr * D;
    } else {
        int j = rr - B;
        int src_b, src_k;
        if (j < B) { src_b = j; src_k = 1; }
        else { int idx = j - B; src_b = idx / (R - 2); src_k = 2 + idx % (R - 2); }
        src_row = (size_t)src_b * R + src_k;
        dst = g_targets + (size_t)j * D;
    }
    const float4* src = (const float4*)(f + src_row * D);
    int n4 = D >> 2;
    for (int d4 = t; d4 < n4; d4 += 64) {
        float4 v = src[d4];
        __nv_bfloat162 lo = __floats2bfloat162_rn(v.x, v.y);
        __nv_bfloat162 hi = __floats2bfloat162_rn(v.z, v.w);
        ((__nv_bfloat162*)dst)[d4 * 2 + 0] = lo;
        ((__nv_bfloat162*)dst)[d4 * 2 + 1] = hi;
    }
}

// ---------------------------------------------------------------------------
// Kernel 2: per-anchor stats — norms, cosines, KL vs softmax(scores), diag dot
// ---------------------------------------------------------------------------
__global__ void stats_kernel(const float* __restrict__ f,
                             const float* __restrict__ scores,
                             int B, int R, int D) {
    int b = blockIdx.x, t = threadIdx.x;  // 128 threads
    const float2* base2 = (const float2*)(f + (size_t)b * R * D);
    int D2 = D >> 1;
    __shared__ float s_dot[32], s_nrm[32], s_red[8];

    for (int k = 0; k < R; k++) {
        float dp = 0.f, sq = 0.f;
        for (int d = t; d < D2; d += 128) {
            float2 xa = base2[d];
            float2 x  = base2[(size_t)k * D2 + d];
            dp += xa.x * x.x + xa.y * x.y;
            sq += x.x * x.x + x.y * x.y;
        }
        #pragma unroll
        for (int o = 16; o > 0; o >>= 1) {
            dp += __shfl_down_sync(0xffffffffu, dp, o);
            sq += __shfl_down_sync(0xffffffffu, sq, o);
        }
        if ((t & 31) == 0) { s_red[t >> 5] = dp; s_red[4 + (t >> 5)] = sq; }
        __syncthreads();
        if (t == 0) {
            s_dot[k] = s_red[0] + s_red[1] + s_red[2] + s_red[3];
            s_nrm[k] = s_red[4] + s_red[5] + s_red[6] + s_red[7];
        }
        __syncthreads();
    }

    if (t < 32) {
        int k = t;
        bool valid = (k >= 1 && k < R);
        float an = fmaxf(sqrtf(s_nrm[0]), C_EPS);
        float cosv = valid ? s_dot[k] / (an * fmaxf(sqrtf(s_nrm[k]), C_EPS)) : -1e30f;
        float sc   = valid ? scores[(size_t)b * (R - 1) + (k - 1)] : -1e30f;

        float cmax = cosv, smax = sc;
        #pragma unroll
        for (int o = 16; o > 0; o >>= 1) {
            cmax = fmaxf(cmax, __shfl_xor_sync(0xffffffffu, cmax, o));
            smax = fmaxf(smax, __shfl_xor_sync(0xffffffffu, smax, o));
        }
        float c_e  = valid ? __expf(cosv - cmax) : 0.f;
        float ce_e = valid ? __expf(sc - smax)   : 0.f;
        float csum = c_e, ssum = ce_e;
        #pragma unroll
        for (int o = 16; o > 0; o >>= 1) {
            csum += __shfl_xor_sync(0xffffffffu, csum, o);
            ssum += __shfl_xor_sync(0xffffffffu, ssum, o);
        }
        float emb_log = cosv - cmax - logf(csum);
        float lce     = sc - smax - logf(ssum);
        float ce      = ce_e / ssum;
        float term    = valid ? ce * (lce - emb_log) : 0.f;
        #pragma unroll
        for (int o = 16; o > 0; o >>= 1)
            term += __shfl_xor_sync(0xffffffffu, term, o);
        if (t == 0) {
            g_kl[b]   = term / (float)(R - 1);
            g_diag[b] = s_dot[1];
        }
    }
}

// ---------------------------------------------------------------------------
// Kernel 3: fused GEMM + online logsumexp.
// BM=BN=128, K=256.  8 warps in a 4x2 grid; warp tile 32 rows x 64 cols
// (2 A-LDSM + 4 B-LDSM per 16 MMA per k-step).  Explicit 2-stage register
// pipeline over k.  A-tile resident; B-tile double-buffered cp.async.
// Padded smem row stride 528B (conflict-free LDSM) — layout proven in R4.
// ---------------------------------------------------------------------------
#define BM 128
#define BN 128
#define SSTRIDE 528
#define TILE_SMEM (128 * SSTRIDE)    // 67584 B
#define GEMM_SMEM (3 * TILE_SMEM)    // A + 2x B = 202752 B

__device__ __forceinline__ void load_tile_async(uint32_t sbase,
                                                const __nv_bfloat16* gsrc,
                                                int tid) {
    const char* src = (const char*)gsrc;
    #pragma unroll
    for (int i = 0; i < 16; i++) {
        int c   = i * 256 + tid;       // 4096 x 16B chunks
        int row = c >> 5, col = c & 31;
        cp_async16(sbase + row * SSTRIDE + col * 16, src + row * 512 + col * 16);
    }
    cp_commit();
}

__global__ __launch_bounds__(256, 1)
void gemm_lse_kernel(const float* __restrict__ logit_scale_ptr,
                     int B, int ntiles) {
    extern __shared__ char smem[];
    const int tid  = threadIdx.x;
    const int warp = tid >> 5, lane = tid & 31;
    const int split = blockIdx.x;      // 0..NSPLIT-1
    const int mtile = blockIdx.y;      // 0..B/128-1
    const float scale = __ldg(logit_scale_ptr);

    const uint32_t As_b  = (uint32_t)__cvta_generic_to_shared(smem);
    const uint32_t Bs_b0 = As_b + TILE_SMEM;
    const uint32_t Bs_b1 = As_b + 2 * TILE_SMEM;

    // work partition over N tiles (544 total -> 17 per split)
    int tps = ntiles / NSPLIT, rem = ntiles % NSPLIT;
    int my_nt = tps + (split < rem ? 1 : 0);
    int tbase = split * tps + (split < rem ? split : rem);

    // A tile (anchors) load — stays resident
    load_tile_async(As_b, g_anchor + (size_t)mtile * BM * DD, tid);
    // B tile 0
    if (my_nt > 0)
        load_tile_async(Bs_b0, g_targets + (size_t)(tbase)*BN * DD, tid);

    // ldmatrix in-tile offsets (same q-mapping as the R4-proven kernel)
    const int q = lane >> 3;
    const int wrow = warp & 3;        // A row block (32 rows)
    const int wcol = warp >> 2;       // B col block (64 cols)
    const uint32_t a_off = (uint32_t)((wrow * 32 + (lane & 7) + (q & 1) * 8) * SSTRIDE
                                      + (q >> 1) * 16);
    const uint32_t b_off = (uint32_t)((wcol * 64 + (lane & 7) + (q >> 1) * 8) * SSTRIDE
                                      + (q & 1) * 16);

    // online lse state: 4 row-groups per lane
    float m4[4] = {-1e30f, -1e30f, -1e30f, -1e30f};
    float l4[4] = {0.f, 0.f, 0.f, 0.f};

    for (int i = 0; i < my_nt; i++) {
        if (i + 1 < my_nt)
            load_tile_async((i & 1) ? Bs_b0 : Bs_b1,
                            g_targets + (size_t)(tbase + i + 1) * BN * DD, tid);
        if (i + 1 < my_nt) cp_wait<1>(); else cp_wait<0>();
        __syncthreads();

        const uint32_t Bb = (i & 1) ? Bs_b1 : Bs_b0;
        float c[2][8][4];
        #pragma unroll
        for (int mi = 0; mi < 2; mi++)
            #pragma unroll
            for (int ni = 0; ni < 8; ni++) {
                c[mi][ni][0] = 0.f; c[mi][ni][1] = 0.f;
                c[mi][ni][2] = 0.f; c[mi][ni][3] = 0.f;
            }

        // 2-stage register pipeline over the 16 k-steps
        uint32_t af[2][2][4], bf[2][4][4];
        ldsm4(af[0][0], As_b + a_off);
        ldsm4(af[0][1], As_b + a_off + 16 * SSTRIDE);
        ldsm4(bf[0][0], Bb + b_off);
        ldsm4(bf[0][1], Bb + b_off + 16 * SSTRIDE);
        ldsm4(bf[0][2], Bb + b_off + 32 * SSTRIDE);
        ldsm4(bf[0][3], Bb + b_off + 48 * SSTRIDE);

        #pragma unroll
        for (int k = 0; k < 16; k++) {
            const int s = k & 1;
            if (k < 15) {
                const int ss = s ^ 1;
                const uint32_t ko = (uint32_t)((k + 1) * 32);
                ldsm4(af[ss][0], As_b + a_off + ko);
                ldsm4(af[ss][1], As_b + a_off + 16 * SSTRIDE + ko);
                ldsm4(bf[ss][0], Bb + b_off + ko);
                ldsm4(bf[ss][1], Bb + b_off + 16 * SSTRIDE + ko);
                ldsm4(bf[ss][2], Bb + b_off + 32 * SSTRIDE + ko);
                ldsm4(bf[ss][3], Bb + b_off + 48 * SSTRIDE + ko);
            }
            #pragma unroll
            for (int mi = 0; mi < 2; mi++)
                #pragma unroll
                for (int nj = 0; nj < 4; nj++) {
                    mma16816(c[mi][2 * nj],     af[s][mi], bf[s][nj][0], bf[s][nj][1]);
                    mma16816(c[mi][2 * nj + 1], af[s][mi], bf[s][nj][2], bf[s][nj][3]);
                }
        }

        // ---- scale + online logsumexp (4 row-groups: mi x {lo,hi})
        #pragma unroll
        for (int mi = 0; mi < 2; mi++)
            #pragma unroll
            for (int ni = 0; ni < 8; ni++) {
                c[mi][ni][0] *= scale; c[mi][ni][1] *= scale;
                c[mi][ni][2] *= scale; c[mi][ni][3] *= scale;
            }

        float vmax[4];
        #pragma unroll
        for (int g = 0; g < 4; g++) {
            const int mi = g >> 1, h = g & 1;
            float vm = -1e30f;
            #pragma unroll
            for (int ni = 0; ni < 8; ni++)
                vm = fmaxf(vm, fmaxf(c[mi][ni][2 * h], c[mi][ni][2 * h + 1]));
            vm = fmaxf(vm, __shfl_xor_sync(0xffffffffu, vm, 1));
            vm = fmaxf(vm, __shfl_xor_sync(0xffffffffu, vm, 2));
            vmax[g] = vm;
        }
        bool need = (vmax[0] > m4[0] - 25.f) || (vmax[1] > m4[1] - 25.f)
                 || (vmax[2] > m4[2] - 25.f) || (vmax[3] > m4[3] - 25.f);
        if (__ballot_sync(0xffffffffu, need)) {
            #pragma unroll
            for (int g = 0; g < 4; g++) {
                const int mi = g >> 1, h = g & 1;
                float nm = fmaxf(m4[g], vmax[g]);
                float s = 0.f;
                #pragma unroll
                for (int ni = 0; ni < 8; ni++)
                    s += __expf(c[mi][ni][2 * h] - nm) + __expf(c[mi][ni][2 * h + 1] - nm);
                s += __shfl_xor_sync(0xffffffffu, s, 1);
                s += __shfl_xor_sync(0xffffffffu, s, 2);
                l4[g] = l4[g] * __expf(m4[g] - nm) + s;
                m4[g] = nm;
            }
        }
        __syncthreads();
    }

    if ((lane & 3) == 0) {
        #pragma unroll
        for (int g = 0; g < 4; g++) {
            const int mi = g >> 1, h = g & 1;
            int row = mtile * BM + wrow * 32 + mi * 16 + (lane >> 2) + h * 8;
            size_t o = (size_t)split * B + row;
            // 2 warps (wcol 0/1) cover the same rows on different col halves:
            // only wcol 0 would collide with wcol 1 — give each its own slot?
            // No: rows are shared between wcol=0 and wcol=1 warps.  Merge the
            // two col-halves through shared memory instead.
            (void)o;
        }
    }

    // ---- combine the two column-half warps (wcol 0 & 1) for each row group
    __shared__ float s_m[256], s_l[256];   // indexed by [wcol*128 + wrow*32 + row_in_32]
    if ((lane & 3) == 0) {
        #pragma unroll
        for (int g = 0; g < 4; g++) {
            const int mi = g >> 1, h = g & 1;
            int rloc = wrow * 32 + mi * 16 + (lane >> 2) + h * 8;
            s_m[wcol * 128 + rloc] = m4[g];
            s_l[wcol * 128 + rloc] = l4[g];
        }
    }
    __syncthreads();
    // 256 threads: thread t handles row t&127 for half t>>7 -> only t<128 writes
    if (tid < 128) {
        float m0 = s_m[tid], l0 = s_l[tid];
        float m1 = s_m[128 + tid], l1 = s_l[128 + tid];
        float M = fmaxf(m0, m1);
        float L = l0 * __expf(m0 - M) + l1 * __expf(m1 - M);
        int row = mtile * BM + tid;
        size_t o = (size_t)split * B + row;
        g_part_m[o] = M;
        g_part_l[o] = L;
    }
}

// ---------------------------------------------------------------------------
// Kernel 4: merge split partials -> lse, combine with KL + diag, block-reduce
// ---------------------------------------------------------------------------
__global__ void merge_kernel(const float* __restrict__ logit_scale_ptr, int B) {
    int b = blockIdx.x * 256 + threadIdx.x;
    float scale = __ldg(logit_scale_ptr);
    float M = -1e30f;
    #pragma unroll
    for (int i = 0; i < NSPLIT; i++) M = fmaxf(M, g_part_m[(size_t)i * B + b]);
    float L = 0.f;
    #pragma unroll
    for (int i = 0; i < NSPLIT; i++)
        L += g_part_l[(size_t)i * B + b] * __expf(g_part_m[(size_t)i * B + b] - M);
    float lse = M + logf(L);
    float val = C_BETA * g_kl[b] + C_ALPHA * (lse - scale * g_diag[b]);

    __shared__ float sm[256];
    sm[threadIdx.x] = val;
    __syncthreads();
    #pragma unroll
    for (int s = 128; s > 0; s >>= 1) {
        if (threadIdx.x < s) sm[threadIdx.x] += sm[threadIdx.x + s];
        __syncthreads();
    }
    if (threadIdx.x == 0) g_bsum[blockIdx.x] = sm[0];
}

__global__ void final_kernel(float* out, int B, int nb) {
    if (threadIdx.x == 0) {
        float s = 0.f;
        for (int i = 0; i < nb; i++) s += g_bsum[i];
        out[0] = s / (float)B;
    }
}

// ---------------------------------------------------------------------------
extern "C" void kernel_launch(void* const* d_in, const int* in_sizes, int n_in,
                              void* d_out, int out_size) {
    const float* features = (const float*)d_in[0];
    const float* scores   = (const float*)d_in[1];
    const float* lscale   = (const float*)d_in[3];
    float* out = (float*)d_out;

    int B   = in_sizes[2];
    int Rm1 = in_sizes[1] / B;
    int R   = Rm1 + 1;
    int D   = in_sizes[0] / (B * R);   // 256

    cudaFuncSetAttribute(gemm_lse_kernel,
                         cudaFuncAttributeMaxDynamicSharedMemorySize, GEMM_SMEM);

    // 1. bf16 conversion / target reorder
    convert_kernel<<<B * R, 64>>>(features, B, R, D);
    // 2. norms / cos / KL / diagonal (fp32)
    stats_kernel<<<B, 128>>>(features, scores, B, R, D);
    // 3. fused GEMM + online logsumexp
    int Ntot   = B * Rm1;          // 69632
    int ntiles = Ntot / BN;        // 544
    dim3 grid(NSPLIT, B / BM);     // (32, 32)
    gemm_lse_kernel<<<grid, 256, GEMM_SMEM>>>(lscale, B, ntiles);
    // 4. merge + reduce
    int nb = B / 256;              // 16
    merge_kernel<<<nb, 256>>>(lscale, B);
    final_kernel<<<1, 32>>>(out, B, nb);
}

// round 12
// speedup vs baseline: 1.1672x; 1.1076x over previous
#include <cuda_runtime.h>
#include <cuda_bf16.h>
#include <cstdint>
#include <cstddef>

// ---------------------------------------------------------------------------
// MultiCELoss: KL(softmax(scores) || softmax(cos(anchor,tgt)))/(R-1) mean
//            + ALPHA * mean_b( lse_j(scale * a_b . t_j) - scale * a_b . t_b )
// B=4096, R=18, D=256.  Heavy part: 4096 x 69632 x 256 bf16 mma.sync GEMM
// fused with per-row online logsumexp.  Harness targets compute_103 (no 'a')
// so tcgen05 is unavailable; measured HMMA floor ~16 cyc/instr/SMSP -> the
// GEMM mainloop (proven in R10) is kept verbatim.  Non-GEMM work fully fused:
// prep = convert+stats one-pass; merge+final folded into the GEMM tail with
// deterministic counter-based completion (no spin-waits, no float atomics).
// ---------------------------------------------------------------------------

#define C_ALPHA 0.2f
#define C_BETA  1.0f
#define C_EPS   1e-8f

#define MAXB 4096
#define MAXR 18
#define DD   256
#define NSPLIT 32
#define NMT   32          // B/BM mtiles

__device__ __align__(16) __nv_bfloat16 g_anchor[(size_t)MAXB * DD];   // pre-scaled by logit_scale
__device__ __align__(16) __nv_bfloat16 g_targets[(size_t)MAXB * (MAXR - 1) * DD];
__device__ float g_diag[MAXB];       // raw anchor.pos dot (unscaled)
__device__ float g_kl[MAXB];
__device__ float g_part_m[(size_t)NSPLIT * MAXB];
__device__ float g_part_l[(size_t)NSPLIT * MAXB];
__device__ float g_msum[NMT];
__device__ int   g_cnt[NMT + 1];     // [0..NMT-1] per-mtile, [NMT] final

// ---------------------------------------------------------------------------
// PTX helpers
// ---------------------------------------------------------------------------
__device__ __forceinline__ void cp_async16(uint32_t saddr, const void* gaddr) {
    asm volatile("cp.async.cg.shared.global [%0], [%1], 16;\n"
                 :: "r"(saddr), "l"(gaddr) : "memory");
}
__device__ __forceinline__ void cp_commit() {
    asm volatile("cp.async.commit_group;\n" ::: "memory");
}
template <int N>
__device__ __forceinline__ void cp_wait() {
    asm volatile("cp.async.wait_group %0;\n" :: "n"(N) : "memory");
}
__device__ __forceinline__ void ldsm4(uint32_t* r, uint32_t addr) {
    asm volatile("ldmatrix.sync.aligned.m8n8.x4.shared.b16 {%0,%1,%2,%3}, [%4];\n"
                 : "=r"(r[0]), "=r"(r[1]), "=r"(r[2]), "=r"(r[3]) : "r"(addr));
}
__device__ __forceinline__ void mma16816(float* c, const uint32_t* a, uint32_t b0, uint32_t b1) {
    asm volatile("mma.sync.aligned.m16n8k16.row.col.f32.bf16.bf16.f32 "
                 "{%0,%1,%2,%3}, {%4,%5,%6,%7}, {%8,%9}, {%0,%1,%2,%3};\n"
                 : "+f"(c[0]), "+f"(c[1]), "+f"(c[2]), "+f"(c[3])
                 : "r"(a[0]), "r"(a[1]), "r"(a[2]), "r"(a[3]), "r"(b0), "r"(b1));
}

// ---------------------------------------------------------------------------
// Kernel 1 (prep): one pass over features.  grid=B, block=R*32 (18 warps).
// Warp k: dot(anchor,row k) + |row k|^2, then bf16 convert+reorder (anchor
// pre-scaled by logit_scale).  Warp 0 then computes KL + diag.  Block 0 also
// re-zeroes the completion counters for this replay.
// ---------------------------------------------------------------------------
__global__ void prep_kernel(const float* __restrict__ f,
                            const float* __restrict__ scores,
                            const float* __restrict__ lscale,
                            int B, int R, int D) {
    int b = blockIdx.x;
    int warp = threadIdx.x >> 5, lane = threadIdx.x & 31;
    int k = warp;                     // 0..R-1
    __shared__ float s_dot[32], s_nrm[32];

    if (b == 0 && threadIdx.x <= NMT) g_cnt[threadIdx.x] = 0;

    const float4* xr = (const float4*)(f + ((size_t)b * R + k) * D);
    const float4* ar = (const float4*)(f + (size_t)b * R * D);
    float4 x0 = xr[2 * lane], x1 = xr[2 * lane + 1];
    float4 a0 = ar[2 * lane], a1 = ar[2 * lane + 1];

    float dp = a0.x*x0.x + a0.y*x0.y + a0.z*x0.z + a0.w*x0.w
             + a1.x*x1.x + a1.y*x1.y + a1.z*x1.z + a1.w*x1.w;
    float sq = x0.x*x0.x + x0.y*x0.y + x0.z*x0.z + x0.w*x0.w
             + x1.x*x1.x + x1.y*x1.y + x1.z*x1.z + x1.w*x1.w;
    #pragma unroll
    for (int o = 16; o > 0; o >>= 1) {
        dp += __shfl_xor_sync(0xffffffffu, dp, o);
        sq += __shfl_xor_sync(0xffffffffu, sq, o);
    }
    if (lane == 0) { s_dot[k] = dp; s_nrm[k] = sq; }

    // bf16 conversion + reorder (anchor scaled by logit_scale)
    {
        float sc = (k == 0) ? __ldg(lscale) : 1.0f;
        __nv_bfloat16* dst;
        if (k == 0)      dst = g_anchor  + (size_t)b * D;
        else if (k == 1) dst = g_targets + (size_t)b * D;
        else             dst = g_targets + ((size_t)B + (size_t)b * (R - 2) + (k - 2)) * D;
        union { __nv_bfloat162 h[4]; uint4 u; } cv;
        cv.h[0] = __floats2bfloat162_rn(sc * x0.x, sc * x0.y);
        cv.h[1] = __floats2bfloat162_rn(sc * x0.z, sc * x0.w);
        cv.h[2] = __floats2bfloat162_rn(sc * x1.x, sc * x1.y);
        cv.h[3] = __floats2bfloat162_rn(sc * x1.z, sc * x1.w);
        ((uint4*)dst)[lane] = cv.u;
    }
    __syncthreads();

    if (warp == 0) {
        int kk = lane;
        bool valid = (kk >= 1 && kk < R);
        int ki = valid ? kk : 1;
        float an   = fmaxf(sqrtf(s_nrm[0]), C_EPS);
        float cosv = valid ? s_dot[ki] / (an * fmaxf(sqrtf(s_nrm[ki]), C_EPS)) : -1e30f;
        float scv  = valid ? scores[(size_t)b * (R - 1) + (kk - 1)] : -1e30f;

        float cmax = cosv, smax = scv;
        #pragma unroll
        for (int o = 16; o > 0; o >>= 1) {
            cmax = fmaxf(cmax, __shfl_xor_sync(0xffffffffu, cmax, o));
            smax = fmaxf(smax, __shfl_xor_sync(0xffffffffu, smax, o));
        }
        float c_e  = valid ? __expf(cosv - cmax) : 0.f;
        float ce_e = valid ? __expf(scv  - smax) : 0.f;
        float csum = c_e, ssum = ce_e;
        #pragma unroll
        for (int o = 16; o > 0; o >>= 1) {
            csum += __shfl_xor_sync(0xffffffffu, csum, o);
            ssum += __shfl_xor_sync(0xffffffffu, ssum, o);
        }
        float emb_log = cosv - cmax - logf(csum);
        float lce     = scv  - smax - logf(ssum);
        float ce      = ce_e / ssum;
        float term    = valid ? ce * (lce - emb_log) : 0.f;
        #pragma unroll
        for (int o = 16; o > 0; o >>= 1)
            term += __shfl_xor_sync(0xffffffffu, term, o);
        if (lane == 0) {
            g_kl[b]   = term / (float)(R - 1);
            g_diag[b] = s_dot[1];
        }
    }
}

// ---------------------------------------------------------------------------
// Kernel 2: fused GEMM + online logsumexp + deterministic merge/final tail.
// BM=BN=128, K=256.  8 warps (4x2); warp tile 32x64; 2-stage k register
// pipeline; A resident; B double-buffered cp.async; 528B padded smem stride.
// Mainloop identical to the R10-passing kernel (at the HMMA issue floor);
// anchors are pre-scaled so no epilogue scaling is needed.
// ---------------------------------------------------------------------------
#define BM 128
#define BN 128
#define SSTRIDE 528
#define TILE_SMEM (128 * SSTRIDE)    // 67584 B
#define GEMM_SMEM (3 * TILE_SMEM)    // A + 2x B = 202752 B

__device__ __forceinline__ void load_tile_async(uint32_t sbase,
                                                const __nv_bfloat16* gsrc,
                                                int tid) {
    const char* src = (const char*)gsrc;
    #pragma unroll
    for (int i = 0; i < 16; i++) {
        int c   = i * 256 + tid;       // 4096 x 16B chunks
        int row = c >> 5, col = c & 31;
        cp_async16(sbase + row * SSTRIDE + col * 16, src + row * 512 + col * 16);
    }
    cp_commit();
}

__global__ __launch_bounds__(256, 1)
void gemm_lse_kernel(const float* __restrict__ logit_scale_ptr,
                     float* __restrict__ out, int B, int ntiles) {
    extern __shared__ char smem[];
    const int tid  = threadIdx.x;
    const int warp = tid >> 5, lane = tid & 31;
    const int split = blockIdx.x;      // 0..NSPLIT-1
    const int mtile = blockIdx.y;      // 0..NMT-1

    const uint32_t As_b  = (uint32_t)__cvta_generic_to_shared(smem);
    const uint32_t Bs_b0 = As_b + TILE_SMEM;
    const uint32_t Bs_b1 = As_b + 2 * TILE_SMEM;

    // work partition over N tiles (544 total -> 17 per split)
    int tps = ntiles / NSPLIT, rem = ntiles % NSPLIT;
    int my_nt = tps + (split < rem ? 1 : 0);
    int tbase = split * tps + (split < rem ? split : rem);

    // A tile (anchors, pre-scaled) — stays resident
    load_tile_async(As_b, g_anchor + (size_t)mtile * BM * DD, tid);
    if (my_nt > 0)
        load_tile_async(Bs_b0, g_targets + (size_t)(tbase)*BN * DD, tid);

    const int q = lane >> 3;
    const int wrow = warp & 3;        // A row block (32 rows)
    const int wcol = warp >> 2;       // B col block (64 cols)
    const uint32_t a_off = (uint32_t)((wrow * 32 + (lane & 7) + (q & 1) * 8) * SSTRIDE
                                      + (q >> 1) * 16);
    const uint32_t b_off = (uint32_t)((wcol * 64 + (lane & 7) + (q >> 1) * 8) * SSTRIDE
                                      + (q & 1) * 16);

    float m4[4] = {-1e30f, -1e30f, -1e30f, -1e30f};
    float l4[4] = {0.f, 0.f, 0.f, 0.f};

    for (int i = 0; i < my_nt; i++) {
        if (i + 1 < my_nt)
            load_tile_async((i & 1) ? Bs_b0 : Bs_b1,
                            g_targets + (size_t)(tbase + i + 1) * BN * DD, tid);
        if (i + 1 < my_nt) cp_wait<1>(); else cp_wait<0>();
        __syncthreads();

        const uint32_t Bb = (i & 1) ? Bs_b1 : Bs_b0;
        float c[2][8][4];
        #pragma unroll
        for (int mi = 0; mi < 2; mi++)
            #pragma unroll
            for (int ni = 0; ni < 8; ni++) {
                c[mi][ni][0] = 0.f; c[mi][ni][1] = 0.f;
                c[mi][ni][2] = 0.f; c[mi][ni][3] = 0.f;
            }

        uint32_t af[2][2][4], bf[2][4][4];
        ldsm4(af[0][0], As_b + a_off);
        ldsm4(af[0][1], As_b + a_off + 16 * SSTRIDE);
        ldsm4(bf[0][0], Bb + b_off);
        ldsm4(bf[0][1], Bb + b_off + 16 * SSTRIDE);
        ldsm4(bf[0][2], Bb + b_off + 32 * SSTRIDE);
        ldsm4(bf[0][3], Bb + b_off + 48 * SSTRIDE);

        #pragma unroll
        for (int k = 0; k < 16; k++) {
            const int s = k & 1;
            if (k < 15) {
                const int ss = s ^ 1;
                const uint32_t ko = (uint32_t)((k + 1) * 32);
                ldsm4(af[ss][0], As_b + a_off + ko);
                ldsm4(af[ss][1], As_b + a_off + 16 * SSTRIDE + ko);
                ldsm4(bf[ss][0], Bb + b_off + ko);
                ldsm4(bf[ss][1], Bb + b_off + 16 * SSTRIDE + ko);
                ldsm4(bf[ss][2], Bb + b_off + 32 * SSTRIDE + ko);
                ldsm4(bf[ss][3], Bb + b_off + 48 * SSTRIDE + ko);
            }
            #pragma unroll
            for (int mi = 0; mi < 2; mi++)
                #pragma unroll
                for (int nj = 0; nj < 4; nj++) {
                    mma16816(c[mi][2 * nj],     af[s][mi], bf[s][nj][0], bf[s][nj][1]);
                    mma16816(c[mi][2 * nj + 1], af[s][mi], bf[s][nj][2], bf[s][nj][3]);
                }
        }

        // ---- online logsumexp (logits already scaled via anchors)
        float vmax[4];
        #pragma unroll
        for (int g = 0; g < 4; g++) {
            const int mi = g >> 1, h = g & 1;
            float vm = -1e30f;
            #pragma unroll
            for (int ni = 0; ni < 8; ni++)
                vm = fmaxf(vm, fmaxf(c[mi][ni][2 * h], c[mi][ni][2 * h + 1]));
            vm = fmaxf(vm, __shfl_xor_sync(0xffffffffu, vm, 1));
            vm = fmaxf(vm, __shfl_xor_sync(0xffffffffu, vm, 2));
            vmax[g] = vm;
        }
        bool need = (vmax[0] > m4[0] - 25.f) || (vmax[1] > m4[1] - 25.f)
                 || (vmax[2] > m4[2] - 25.f) || (vmax[3] > m4[3] - 25.f);
        if (__ballot_sync(0xffffffffu, need)) {
            #pragma unroll
            for (int g = 0; g < 4; g++) {
                const int mi = g >> 1, h = g & 1;
                float nm = fmaxf(m4[g], vmax[g]);
                float s = 0.f;
                #pragma unroll
                for (int ni = 0; ni < 8; ni++)
                    s += __expf(c[mi][ni][2 * h] - nm) + __expf(c[mi][ni][2 * h + 1] - nm);
                s += __shfl_xor_sync(0xffffffffu, s, 1);
                s += __shfl_xor_sync(0xffffffffu, s, 2);
                l4[g] = l4[g] * __expf(m4[g] - nm) + s;
                m4[g] = nm;
            }
        }
        __syncthreads();
    }

    // ---- combine the two column-half warps (wcol 0 & 1) per row
    __shared__ float s_m[256], s_l[256];
    if ((lane & 3) == 0) {
        #pragma unroll
        for (int g = 0; g < 4; g++) {
            const int mi = g >> 1, h = g & 1;
            int rloc = wrow * 32 + mi * 16 + (lane >> 2) + h * 8;
            s_m[wcol * 128 + rloc] = m4[g];
            s_l[wcol * 128 + rloc] = l4[g];
        }
    }
    __syncthreads();
    if (tid < 128) {
        float m0 = s_m[tid], l0 = s_l[tid];
        float m1 = s_m[128 + tid], l1 = s_l[128 + tid];
        float M = fmaxf(m0, m1);
        float L = l0 * __expf(m0 - M) + l1 * __expf(m1 - M);
        int row = mtile * BM + tid;
        size_t o = (size_t)split * B + row;
        g_part_m[o] = M;
        g_part_l[o] = L;
    }
    __syncthreads();

    // ---- deterministic merge tail: last split-CTA of this mtile merges
    __shared__ int s_flag;
    if (tid == 0) {
        __threadfence();
        int old = atomicAdd(&g_cnt[mtile], 1);
        s_flag = (old == NSPLIT - 1) ? 1 : 0;
    }
    __syncthreads();
    if (!s_flag) return;
    __threadfence();   // acquire: see all splits' partials

    float scale = __ldg(logit_scale_ptr);
    float val = 0.f;
    if (tid < 128) {
        int row = mtile * BM + tid;
        float M = -1e30f;
        #pragma unroll
        for (int i = 0; i < NSPLIT; i++) M = fmaxf(M, g_part_m[(size_t)i * B + row]);
        float L = 0.f;
        #pragma unroll
        for (int i = 0; i < NSPLIT; i++)
            L += g_part_l[(size_t)i * B + row] * __expf(g_part_m[(size_t)i * B + row] - M);
        float lse = M + logf(L);
        val = C_BETA * g_kl[row] + C_ALPHA * (lse - scale * g_diag[row]);
    }
    // fixed-tree reduce over 128 lanes' vals (threads 128..255 contribute 0)
    __shared__ float s_red[256];
    s_red[tid] = val;
    __syncthreads();
    #pragma unroll
    for (int s = 128; s > 0; s >>= 1) {
        if (tid < s) s_red[tid] += s_red[tid + s];
        __syncthreads();
    }
    if (tid == 0) {
        g_msum[mtile] = s_red[0];
        __threadfence();
        int old = atomicAdd(&g_cnt[NMT], 1);
        if (old == NMT - 1) {
            __threadfence();
            float tot = 0.f;
            #pragma unroll
            for (int i = 0; i < NMT; i++) tot += g_msum[i];
            out[0] = tot / (float)B;
        }
    }
}

// ---------------------------------------------------------------------------
extern "C" void kernel_launch(void* const* d_in, const int* in_sizes, int n_in,
                              void* d_out, int out_size) {
    const float* features = (const float*)d_in[0];
    const float* scores   = (const float*)d_in[1];
    const float* lscale   = (const float*)d_in[3];
    float* out = (float*)d_out;

    int B   = in_sizes[2];
    int Rm1 = in_sizes[1] / B;
    int R   = Rm1 + 1;
    int D   = in_sizes[0] / (B * R);   // 256

    cudaFuncSetAttribute(gemm_lse_kernel,
                         cudaFuncAttributeMaxDynamicSharedMemorySize, GEMM_SMEM);

    // 1. fused prep: stats (KL/diag) + bf16 conversion (anchor pre-scaled)
    //    + completion-counter reset for this replay
    prep_kernel<<<B, R * 32>>>(features, scores, lscale, B, R, D);
    // 2. fused GEMM + online logsumexp + merge/final tail
    int ntiles = (B * Rm1) / BN;       // 544
    dim3 grid(NSPLIT, B / BM);         // (32, 32)
    gemm_lse_kernel<<<grid, 256, GEMM_SMEM>>>(lscale, out, B, ntiles);
}